// round 10
// baseline (speedup 1.0000x reference)
#include <cuda_runtime.h>

// DTW loss: 32 independent 1024x1024 wavefront DPs, fused with path-loss
// accumulation (W[i,j] = w(i,j) + W[argmin-pred]) -> no backtrack needed.
//
// R9 = R8 retry (previous round died to a broker infra failure, not the
// kernel): R7's branch-free chunked pipeline split across a 2-CTA cluster:
// 16 stages x 64 rows (RR=2/thread), 2 warps/SMSP, 128 SMs busy.
// Cross-CTA boundary uses DSMEM remote stores + remote release counter
// (consumer polls its OWN smem). Micro-opts: fmin-chained argmin, packed
// float2 targets (1 LDS.64/step).

#define NN 1024
#define MM 1024
#define RR 2                 // rows per thread
#define TT 256               // threads per CTA
#define NWARP 8
#define CLUSTER 2
#define BAND 64              // rows per warp stage
#define RING 2048
#define SCH 16               // diagonals per sync chunk

#define FINF (__int_as_float(0x7f800000))
#define SENT 1.0e18f

__device__ float g_partial[64];

static __forceinline__ __device__ float fsqrt_approx(float x) {
    float r;
    asm("sqrt.approx.f32 %0, %1;" : "=f"(r) : "f"(x));
    return r;
}
static __forceinline__ __device__ unsigned smem_u32(const void* p) {
    return (unsigned)__cvta_generic_to_shared(p);
}

// packed target array: logical j in [-PADF, MM-1+PADF], swizzled idx = u+u/4
#define PADF 64
#define STCNT (PADF + MM + PADF + 1)      // 1153 logical entries
#define STN2  1472                        // swizzled float2 capacity
#define NRING 8                           // slots 0..6 local, slot 7 incoming
#define SMEM_BYTES (NRING * RING * 8 + STN2 * 8 + 32)

__global__ void __launch_bounds__(TT, 1) __cluster_dims__(CLUSTER, 1, 1)
dtw_forward_kernel(const float* __restrict__ preds,
                   const float* __restrict__ targs,
                   const float* __restrict__ subcoef)
{
    extern __shared__ unsigned char smem_raw[];
    float2*   ring = (float2*)smem_raw;               // [NRING][RING]
    float2*   sT   = (float2*)(ring + NRING * RING);  // [STN2] swizzled+padded
    unsigned* cnt  = (unsigned*)(sT + STN2);          // [8] progress counters

    const int half = blockIdx.x & 1;                  // cluster rank
    const int b    = blockIdx.x >> 1;                 // batch
    const int tid  = threadIdx.x;
    const int lane = tid & 31;
    const int warp = tid >> 5;
    const int g    = half * NWARP + warp;             // global stage 0..15

    const float* __restrict__ pb = preds + (size_t)b * NN * 4;
    const float* __restrict__ tb = targs + (size_t)b * MM * 4;

    // stage packed targets with sentinel pad
    for (int u = tid; u < STCNT; u += TT) {
        int j = u - PADF;
        int idx = u + (u >> 2);
        bool in = (unsigned)j < (unsigned)MM;
        int jc = in ? j : 0;
        sT[idx] = in ? make_float2(tb[jc * 4 + 0], tb[jc * 4 + 1])
                     : make_float2(SENT, SENT);
    }
    if (tid < NRING) cnt[tid] = 0;

    const float s0 = subcoef[0];
    const float s1 = subcoef[1];

    const int i0g = half * (NN / 2) + tid * RR;       // first owned global row
    float px[RR], py[RR];
#pragma unroll
    for (int r = 0; r < RR; ++r) {
        px[r] = pb[(i0g + r) * 4 + 0];
        py[r] = pb[(i0g + r) * 4 + 1];
    }

    float D1[RR], D2[RR], W1[RR], W2[RR];
#pragma unroll
    for (int r = 0; r < RR; ++r) { D1[r] = FINF; D2[r] = FINF; W1[r] = 0.f; W2[r] = 0.f; }

    // diag-(k-2) neighbor-row cache; stage0/lane0 seeds 0 for cell (0,0)
    float pD = (g == 0 && lane == 0) ? 0.f : FINF;
    float pW = 0.f;

    const bool     lane0   = (lane == 0);
    const bool     ringOn  = (g != 0);                    // uniform per warp
    const unsigned pubFlag = (g < NWARP * CLUSTER - 1 && lane == 31) ? 1u : 0u;

    // producer warp w writes slot w; CTA0 warp7 writes CTA1's slot 7 (DSMEM)
    const int dstRank = (warp == NWARP - 1 && half == 0) ? 1 : half;
    unsigned pubRing, pubCnt;
    {
        unsigned rl = smem_u32(&ring[warp * RING]);
        unsigned cl = smem_u32(&cnt[warp]);
        asm("mapa.shared::cluster.u32 %0, %1, %2;" : "=r"(pubRing) : "r"(rl), "r"(dstRank));
        asm("mapa.shared::cluster.u32 %0, %1, %2;" : "=r"(pubCnt)  : "r"(cl), "r"(dstRank));
    }
    // consumer warp w reads slot w-1; warp0 reads incoming slot 7
    const int srcIdx = (warp == 0) ? 7 : (warp - 1);
    const float2*  srcRing = &ring[srcIdx * RING];
    const unsigned prevCnt = smem_u32(&cnt[srcIdx]);

    __syncthreads();
    asm volatile("barrier.cluster.arrive.aligned;" ::: "memory");
    asm volatile("barrier.cluster.wait.aligned;" ::: "memory");

    const int kstart = g * BAND;

    // chunk-0 poll (uniform) + peel of srcRing[kstart-2] for pD
    if (ringOn) {
        const int need = kstart + SCH - 1;
        unsigned c;
        asm volatile("ld.acquire.cluster.shared.u32 %0, [%1];" : "=r"(c) : "r"(prevCnt));
        while ((int)c < need) {
            __nanosleep(32);
            asm volatile("ld.acquire.cluster.shared.u32 %0, [%1];" : "=r"(c) : "r"(prevCnt));
        }
        if (lane0) {
            float2 e = srcRing[(kstart - 2) & (RING - 1)];
            pD = e.x; pW = e.y;
        }
    }

    // sliding target window: after in-loop shift, t[rr] = sT[j0 - rr]
    float2 t0, t1;
    {
        int u = (kstart - i0g) - 1 + PADF;
        int ii = u + (u >> 2);
        t0 = sT[ii];
        t1 = make_float2(SENT, SENT);
    }

    // ---- branch-free step body -------------------------------------------
#define DTW_STEP(KK, USE_RING) do {                                          \
    const int k_ = (KK);                                                     \
    float nD1 = __shfl_up_sync(0xffffffffu, D1[RR - 1], 1);                  \
    float nW1 = __shfl_up_sync(0xffffffffu, W1[RR - 1], 1);                  \
    if (USE_RING) {                                                          \
        float2 e_ = srcRing[(k_ - 1) & (RING - 1)];  /* broadcast LDS */     \
        float rD_ = ringOn ? e_.x : FINF;                                    \
        float rW_ = ringOn ? e_.y : 0.f;                                     \
        nD1 = lane0 ? rD_ : nD1;                                             \
        nW1 = lane0 ? rW_ : nW1;                                             \
    } else {                                                                 \
        nD1 = lane0 ? FINF : nD1;                                            \
        nW1 = lane0 ? 0.f  : nW1;                                            \
    }                                                                        \
    const float nD2 = pD, nW2 = pW;                                          \
    pD = nD1; pW = nW1;                                                      \
    {   /* slide packed target window, load sT[j0] */                        \
        const int u_ = (k_ - i0g) + PADF;                                    \
        const int ii_ = u_ + (u_ >> 2);                                      \
        t1 = t0;                                                             \
        t0 = sT[ii_];                                                        \
    }                                                                        \
    _Pragma("unroll")                                                        \
    for (int rr = RR - 1; rr >= 0; --rr) {                                   \
        float up, dg, wu, wd;                                                \
        if (rr == 0) { up = nD1; dg = nD2; wu = nW1; wd = nW2; }             \
        else         { up = D1[rr - 1]; dg = D2[rr - 1];                     \
                       wu = W1[rr - 1]; wd = W2[rr - 1]; }                   \
        const float lf = D1[rr];                                             \
        const float wl = W1[rr];                                             \
        const float txv = (rr == 0) ? t0.x : t1.x;                           \
        const float tyv = (rr == 0) ? t0.y : t1.y;                           \
        const float dx = px[rr] - txv;                                       \
        const float dy = py[rr] - tyv;                                       \
        const float c_ = fsqrt_approx(dx * dx + dy * dy);                    \
        const float w_ = fabsf(dx) * s0 + fabsf(dy) * s1;                    \
        const float m1 = fminf(up, lf);                                      \
        const float best = fminf(dg, m1);                                    \
        float ws = (up <= lf) ? wu : wl;   /* first-min-wins [dg,up,lf] */   \
        ws = (dg <= m1) ? wd : ws;                                           \
        D2[rr] = D1[rr]; D1[rr] = c_ + best;                                 \
        W2[rr] = W1[rr]; W1[rr] = w_ + ws;                                   \
    }                                                                        \
    /* predicated publish (local or DSMEM remote): no divergent branch */    \
    {                                                                        \
        unsigned long long v_;                                               \
        asm("mov.b64 %0, {%1, %2};" : "=l"(v_)                               \
            : "f"(D1[RR - 1]), "f"(W1[RR - 1]));                             \
        asm volatile("{\n\t.reg .pred p;\n\tsetp.ne.u32 p, %0, 0;\n\t"       \
                     "@p st.weak.shared::cluster.b64 [%1], %2;\n\t}"         \
                     :: "r"(pubFlag),                                        \
                        "r"(pubRing + (unsigned)((k_ & (RING - 1)) * 8)),    \
                        "l"(v_) : "memory");                                 \
    }                                                                        \
} while (0)

#define DTW_RELEASE(VAL) do {                                                \
    asm volatile("{\n\t.reg .pred p;\n\tsetp.ne.u32 p, %0, 0;\n\t"           \
                 "@p st.release.cluster.shared::cluster.u32 [%1], %2;\n\t}"  \
                 :: "r"(pubFlag), "r"(pubCnt), "r"((unsigned)(VAL))          \
                 : "memory");                                                \
} while (0)
    // ----------------------------------------------------------------------

    // Phase A: MM/SCH = 64 chunks x SCH steps, ring-fed
    for (int c = 0; c < MM / SCH; ++c) {
        const int kbase = kstart + c * SCH;
        if (ringOn & (c != 0)) {                      // uniform poll per chunk
            const int need = kbase + SCH - 1;
            unsigned cv;
            asm volatile("ld.acquire.cluster.shared.u32 %0, [%1];" : "=r"(cv) : "r"(prevCnt));
            while ((int)cv < need) {
                __nanosleep(32);
                asm volatile("ld.acquire.cluster.shared.u32 %0, [%1];" : "=r"(cv) : "r"(prevCnt));
            }
        }
#pragma unroll 4
        for (int s = 0; s < SCH; ++s) DTW_STEP(kbase + s, true);
        DTW_RELEASE(kbase + SCH);
    }

    // Phase B: BAND-1 = 63 steps, neighbor statically FINF
    {
        int kb = kstart + MM;
        for (int c = 0; c < 4; ++c) {
            const int lim = (c == 3) ? (SCH - 1) : SCH;
#pragma unroll 4
            for (int s = 0; s < lim; ++s) DTW_STEP(kb + s, false);
            kb += lim;
            DTW_RELEASE(kb);
        }
    }

    if (half == 1 && tid == TT - 1)    // global row N-1: W1[1] == W[N-1][M-1]
        g_partial[b] = W1[RR - 1];

    // keep cluster smem alive until all remote traffic has landed
    asm volatile("barrier.cluster.arrive.aligned;" ::: "memory");
    asm volatile("barrier.cluster.wait.aligned;" ::: "memory");
}

__global__ void dtw_reduce_kernel(float* __restrict__ out, int B)
{
    int l = threadIdx.x;
    float s = 0.f;
    if (l < B)      s += g_partial[l];
    if (l + 32 < B) s += g_partial[l + 32];
#pragma unroll
    for (int o = 16; o; o >>= 1) s += __shfl_xor_sync(0xffffffffu, s, o);
    if (l == 0) out[0] = s;
}

extern "C" void kernel_launch(void* const* d_in, const int* in_sizes, int n_in,
                              void* d_out, int out_size)
{
    const float* preds   = (const float*)d_in[0];
    const float* targs   = (const float*)d_in[1];
    const float* subcoef = (const float*)d_in[2];
    float* out = (float*)d_out;

    int B = in_sizes[0] / (NN * 4);
    if (B < 1) B = 1;
    if (B > 64) B = 64;

    cudaFuncSetAttribute(dtw_forward_kernel,
                         cudaFuncAttributeMaxDynamicSharedMemorySize, SMEM_BYTES);

    dtw_forward_kernel<<<CLUSTER * B, TT, SMEM_BYTES>>>(preds, targs, subcoef);
    dtw_reduce_kernel<<<1, 32>>>(out, B);
}

// round 11
// speedup vs baseline: 1.5543x; 1.5543x over previous
#include <cuda_runtime.h>

// DTW loss: 32 independent 1024x1024 wavefront DPs, fused with path-loss
// accumulation (W[i,j] = w(i,j) + W[argmin-pred]) -> no backtrack needed.
//
// R10: R7's single-CTA branch-free chunked pipeline (8 warps x RR=4,
// 2 warps/SMSP) + instruction diet:
//   - fmin-chained argmin (identical to first-min-wins, -2 inst/cell)
//   - packed float2 targets (1 LDS.64 + 1 addr chain per step)
//   - no ring-index masking (k < RING statically)
//   - SCH=16 (skew 144/stage instead of 160)

#define NN 1024
#define MM 1024
#define TT 256               // threads per block
#define NWARP 8
#define BAND 128             // rows per warp stage (RR=4 per thread)
#define RING 2048
#define SCH 16               // diagonals per sync chunk

#define FINF (__int_as_float(0x7f800000))
#define SENT 1.0e18f

__device__ float g_partial[64];

static __forceinline__ __device__ float fsqrt_approx(float x) {
    float r;
    asm("sqrt.approx.f32 %0, %1;" : "=f"(r) : "f"(x));
    return r;
}
static __forceinline__ __device__ unsigned smem_u32(const void* p) {
    return (unsigned)__cvta_generic_to_shared(p);
}

// packed target array: logical j in [-PADF, 1150], swizzled idx = u + u/4
#define PADF 127
#define STN2 1600
#define RING_F2 (7 * RING)
#define SMEM_BYTES (RING_F2 * 8 + STN2 * 8 + 8 * 4)

__global__ void __launch_bounds__(TT, 1)
dtw_forward_kernel(const float* __restrict__ preds,
                   const float* __restrict__ targs,
                   const float* __restrict__ subcoef)
{
    extern __shared__ unsigned char smem_raw[];
    float2*   ring = (float2*)smem_raw;               // [7][RING]
    float2*   sT   = (float2*)(ring + RING_F2);       // [STN2] swizzled+padded
    unsigned* cnt  = (unsigned*)(sT + STN2);          // [8] progress counters

    const int b    = blockIdx.x;
    const int tid  = threadIdx.x;
    const int lane = tid & 31;
    const int warp = tid >> 5;

    const float* __restrict__ pb = preds + (size_t)b * NN * 4;
    const float* __restrict__ tb = targs + (size_t)b * MM * 4;

    // stage packed targets with sentinel pad (u in [0, 1277])
    for (int u = tid; u < PADF + MM + (BAND - 1); u += TT) {
        int j = u - PADF;
        int idx = u + (u >> 2);
        bool in = (unsigned)j < (unsigned)MM;
        int jc = in ? j : 0;
        sT[idx] = in ? make_float2(tb[jc * 4 + 0], tb[jc * 4 + 1])
                     : make_float2(SENT, SENT);
    }
    if (tid < NWARP) cnt[tid] = 0;

    const float s0 = subcoef[0];
    const float s1 = subcoef[1];

    const int i0 = tid * 4;            // first owned row
    float px0 = pb[(i0 + 0) * 4 + 0], py0 = pb[(i0 + 0) * 4 + 1];
    float px1 = pb[(i0 + 1) * 4 + 0], py1 = pb[(i0 + 1) * 4 + 1];
    float px2 = pb[(i0 + 2) * 4 + 0], py2 = pb[(i0 + 2) * 4 + 1];
    float px3 = pb[(i0 + 3) * 4 + 0], py3 = pb[(i0 + 3) * 4 + 1];

    float D1_0 = FINF, D1_1 = FINF, D1_2 = FINF, D1_3 = FINF;
    float D2_0 = FINF, D2_1 = FINF, D2_2 = FINF, D2_3 = FINF;
    float W1_0 = 0.f,  W1_1 = 0.f,  W1_2 = 0.f,  W1_3 = 0.f;
    float W2_0 = 0.f,  W2_1 = 0.f,  W2_2 = 0.f,  W2_3 = 0.f;

    // diag-(k-2) neighbor-row cache; warp0/lane0 seeds 0 for cell (0,0)
    float pD = (warp == 0 && lane == 0) ? 0.f : FINF;
    float pW = 0.f;

    const bool     lane0   = (lane == 0);
    const bool     ringOn  = (warp != 0);
    const unsigned pubFlag = (warp < NWARP - 1 && lane == 31) ? 1u : 0u;
    const unsigned myCnt   = smem_u32(&cnt[warp]);
    const unsigned prevCnt = smem_u32(&cnt[warp > 0 ? warp - 1 : 0]);
    const float2*  srcRing = &ring[(warp > 0 ? warp - 1 : 0) * RING];
    const unsigned pubRing = smem_u32(&ring[(warp < NWARP - 1 ? warp : 0) * RING]);

    __syncthreads();

    const int kstart = warp * BAND;

    // chunk-0 poll (uniform) + peel of srcRing[kstart-2] for pD
    if (ringOn) {
        const int need = kstart + SCH - 1;
        unsigned c;
        asm volatile("ld.acquire.cta.shared.u32 %0, [%1];" : "=r"(c) : "r"(prevCnt));
        while ((int)c < need) {
            __nanosleep(32);
            asm volatile("ld.acquire.cta.shared.u32 %0, [%1];" : "=r"(c) : "r"(prevCnt));
        }
        if (lane0) {
            float2 e = srcRing[kstart - 2];
            pD = e.x; pW = e.y;
        }
    }

    // packed sliding window: after in-loop shift, t{r} = sT[j0 - r]
    float2 t0, t1, t2, t3;
    {
        const int j0f = kstart - i0;
        int u0 = j0f - 1 + PADF;  t0 = sT[u0 + (u0 >> 2)];
        int u1 = j0f - 2 + PADF;  t1 = sT[u1 + (u1 >> 2)];
        int u2 = j0f - 3 + PADF;  t2 = sT[u2 + (u2 >> 2)];
        t3 = make_float2(SENT, SENT);
    }

    // ---- one cell: first-min-wins argmin over [diag, up, left] ----------
#define CELL(PX, PY, TV, UP, DG, WU, WD, LF, WL, OUT_D, OUT_W) do {          \
    const float dx = (PX) - (TV).x;                                          \
    const float dy = (PY) - (TV).y;                                          \
    const float c_ = fsqrt_approx(dx * dx + dy * dy);                        \
    const float w_ = fabsf(dx) * s0 + fabsf(dy) * s1;                        \
    const float m1 = fminf((UP), (LF));                                      \
    float ws = ((UP) <= (LF)) ? (WU) : (WL);                                 \
    ws = ((DG) <= m1) ? (WD) : ws;                                           \
    OUT_D = c_ + fminf((DG), m1);                                            \
    OUT_W = w_ + ws;                                                         \
} while (0)

    // ---- branch-free step body -------------------------------------------
#define DTW_STEP(KK, USE_RING) do {                                          \
    const int k_ = (KK);                                                     \
    float nD1 = __shfl_up_sync(0xffffffffu, D1_3, 1);                        \
    float nW1 = __shfl_up_sync(0xffffffffu, W1_3, 1);                        \
    if (USE_RING) {                                                          \
        float2 e_ = srcRing[k_ - 1];                 /* broadcast LDS.64 */  \
        float rD_ = ringOn ? e_.x : FINF;                                    \
        float rW_ = ringOn ? e_.y : 0.f;                                     \
        nD1 = lane0 ? rD_ : nD1;                                             \
        nW1 = lane0 ? rW_ : nW1;                                             \
    } else {                                                                 \
        nD1 = lane0 ? FINF : nD1;                                            \
        nW1 = lane0 ? 0.f  : nW1;                                            \
    }                                                                        \
    const float nD2 = pD, nW2 = pW;                                          \
    pD = nD1; pW = nW1;                                                      \
    {   /* slide packed target window, load sT[j0] */                        \
        const int u_ = (k_ - i0) + PADF;                                     \
        t3 = t2; t2 = t1; t1 = t0;                                           \
        t0 = sT[u_ + (u_ >> 2)];                                             \
    }                                                                        \
    float oD3, oW3, oD2_, oW2_, oD1_, oW1_, oD0, oW0;                        \
    CELL(px3, py3, t3, D1_2, D2_2, W1_2, W2_2, D1_3, W1_3, oD3, oW3);        \
    CELL(px2, py2, t2, D1_1, D2_1, W1_1, W2_1, D1_2, W1_2, oD2_, oW2_);      \
    CELL(px1, py1, t1, D1_0, D2_0, W1_0, W2_0, D1_1, W1_1, oD1_, oW1_);      \
    CELL(px0, py0, t0, nD1,  nD2,  nW1,  nW2,  D1_0, W1_0, oD0, oW0);        \
    D2_0 = D1_0; D2_1 = D1_1; D2_2 = D1_2; D2_3 = D1_3;                      \
    W2_0 = W1_0; W2_1 = W1_1; W2_2 = W1_2; W2_3 = W1_3;                      \
    D1_0 = oD0;  D1_1 = oD1_; D1_2 = oD2_; D1_3 = oD3;                       \
    W1_0 = oW0;  W1_1 = oW1_; W1_2 = oW2_; W1_3 = oW3;                       \
    /* predicated publish: no divergent branch */                            \
    {                                                                        \
        unsigned long long v_;                                               \
        asm("mov.b64 %0, {%1, %2};" : "=l"(v_) : "f"(D1_3), "f"(W1_3));      \
        asm volatile("{\n\t.reg .pred p;\n\tsetp.ne.u32 p, %0, 0;\n\t"       \
                     "@p st.shared.b64 [%1], %2;\n\t}"                       \
                     :: "r"(pubFlag), "r"(pubRing + (unsigned)(k_ * 8)),     \
                        "l"(v_) : "memory");                                 \
    }                                                                        \
} while (0)

#define DTW_RELEASE(VAL) do {                                                \
    asm volatile("{\n\t.reg .pred p;\n\tsetp.ne.u32 p, %0, 0;\n\t"           \
                 "@p st.release.cta.shared.u32 [%1], %2;\n\t}"               \
                 :: "r"(pubFlag), "r"(myCnt), "r"((unsigned)(VAL))           \
                 : "memory");                                                \
} while (0)
    // ----------------------------------------------------------------------

    // Phase A: MM/SCH = 64 chunks x SCH steps, ring-fed
    for (int c = 0; c < MM / SCH; ++c) {
        const int kbase = kstart + c * SCH;
        if (ringOn & (c != 0)) {                      // uniform poll per chunk
            const int need = kbase + SCH - 1;
            unsigned cv;
            asm volatile("ld.acquire.cta.shared.u32 %0, [%1];" : "=r"(cv) : "r"(prevCnt));
            while ((int)cv < need) {
                __nanosleep(32);
                asm volatile("ld.acquire.cta.shared.u32 %0, [%1];" : "=r"(cv) : "r"(prevCnt));
            }
        }
#pragma unroll 4
        for (int s = 0; s < SCH; ++s) DTW_STEP(kbase + s, true);
        DTW_RELEASE(kbase + SCH);
    }

    // Phase B: BAND-1 = 127 steps, neighbor statically FINF
    {
        int kb = kstart + MM;
        for (int c = 0; c < 8; ++c) {
            const int lim = (c == 7) ? (SCH - 1) : SCH;
#pragma unroll 4
            for (int s = 0; s < lim; ++s) DTW_STEP(kb + s, false);
            kb += lim;
            DTW_RELEASE(kb);
        }
    }

    if (tid == TT - 1)                 // row N-1: D/W slot 3 == W[N-1][M-1]
        g_partial[b] = W1_3;
}

__global__ void dtw_reduce_kernel(float* __restrict__ out, int B)
{
    int l = threadIdx.x;
    float s = 0.f;
    if (l < B)      s += g_partial[l];
    if (l + 32 < B) s += g_partial[l + 32];
#pragma unroll
    for (int o = 16; o; o >>= 1) s += __shfl_xor_sync(0xffffffffu, s, o);
    if (l == 0) out[0] = s;
}

extern "C" void kernel_launch(void* const* d_in, const int* in_sizes, int n_in,
                              void* d_out, int out_size)
{
    const float* preds   = (const float*)d_in[0];
    const float* targs   = (const float*)d_in[1];
    const float* subcoef = (const float*)d_in[2];
    float* out = (float*)d_out;

    int B = in_sizes[0] / (NN * 4);
    if (B < 1) B = 1;
    if (B > 64) B = 64;

    cudaFuncSetAttribute(dtw_forward_kernel,
                         cudaFuncAttributeMaxDynamicSharedMemorySize, SMEM_BYTES);

    dtw_forward_kernel<<<B, TT, SMEM_BYTES>>>(preds, targs, subcoef);
    dtw_reduce_kernel<<<1, 32>>>(out, B);
}

// round 12
// speedup vs baseline: 1.7740x; 1.1414x over previous
#include <cuda_runtime.h>

// DTW loss: 32 independent 1024x1024 wavefront DPs, fused with path-loss
// accumulation (W[i,j] = w(i,j) + W[argmin-pred]) -> no backtrack needed.
//
// R11: R10 + structural register renaming. 4-step groups with explicit
// (D1,W1)<->(D2,W2) role alternation (period 2) and cyclic target-window
// rotation (period 4) eliminate ~22 register-copy MOVs per step. Warp 0
// reads a prefilled FINF dummy ring slot, removing the ringOn selects.
// Phase B padded to 128 steps with one provably-dead dummy step so the
// whole span is exact groups.

#define NN 1024
#define MM 1024
#define TT 256               // threads per block
#define NWARP 8
#define BAND 128             // rows per warp stage (4 rows/thread)
#define RING 2048
#define SCH 16               // diagonals per sync chunk

#define FINF (__int_as_float(0x7f800000))
#define SENT 1.0e18f

__device__ float g_partial[64];

static __forceinline__ __device__ float fsqrt_approx(float x) {
    float r;
    asm("sqrt.approx.f32 %0, %1;" : "=f"(r) : "f"(x));
    return r;
}
static __forceinline__ __device__ unsigned smem_u32(const void* p) {
    return (unsigned)__cvta_generic_to_shared(p);
}

// packed target array: logical j in [-PADF, ...], swizzled idx = u + u/4
#define PADF 127
#define STN2 1600
#define NRING 8              // slots 0..6 producers, slot 7 = FINF dummy
#define SMEM_BYTES (NRING * RING * 8 + STN2 * 8 + 8 * 4)

__global__ void __launch_bounds__(TT, 1)
dtw_forward_kernel(const float* __restrict__ preds,
                   const float* __restrict__ targs,
                   const float* __restrict__ subcoef)
{
    extern __shared__ unsigned char smem_raw[];
    float2*   ring = (float2*)smem_raw;               // [NRING][RING]
    float2*   sT   = (float2*)(ring + NRING * RING);  // [STN2] swizzled+padded
    unsigned* cnt  = (unsigned*)(sT + STN2);          // [8] progress counters

    const int b    = blockIdx.x;
    const int tid  = threadIdx.x;
    const int lane = tid & 31;
    const int warp = tid >> 5;

    const float* __restrict__ pb = preds + (size_t)b * NN * 4;
    const float* __restrict__ tb = targs + (size_t)b * MM * 4;

    // stage packed targets with sentinel pad (u in [0, 1279])
    for (int u = tid; u < PADF + MM + BAND + 1; u += TT) {
        int j = u - PADF;
        int idx = u + (u >> 2);
        bool in = (unsigned)j < (unsigned)MM;
        int jc = in ? j : 0;
        sT[idx] = in ? make_float2(tb[jc * 4 + 0], tb[jc * 4 + 1])
                     : make_float2(SENT, SENT);
    }
    // prefill warp0's dummy ring slot with {FINF, 0}
    for (int u = tid; u < RING; u += TT)
        ring[7 * RING + u] = make_float2(FINF, 0.f);
    if (tid < NWARP) cnt[tid] = 0;

    const float s0 = subcoef[0];
    const float s1 = subcoef[1];

    const int i0 = tid * 4;            // first owned row
    const float px0 = pb[(i0 + 0) * 4 + 0], py0 = pb[(i0 + 0) * 4 + 1];
    const float px1 = pb[(i0 + 1) * 4 + 0], py1 = pb[(i0 + 1) * 4 + 1];
    const float px2 = pb[(i0 + 2) * 4 + 0], py2 = pb[(i0 + 2) * 4 + 1];
    const float px3 = pb[(i0 + 3) * 4 + 0], py3 = pb[(i0 + 3) * 4 + 1];

    // set "a" = current diag (k-1), set "b" = previous diag (k-2); roles
    // alternate each step (new values overwrite the dead k-2 registers)
    float Da0 = FINF, Da1 = FINF, Da2 = FINF, Da3 = FINF;
    float Db0 = FINF, Db1 = FINF, Db2 = FINF, Db3 = FINF;
    float Wa0 = 0.f,  Wa1 = 0.f,  Wa2 = 0.f,  Wa3 = 0.f;
    float Wb0 = 0.f,  Wb1 = 0.f,  Wb2 = 0.f,  Wb3 = 0.f;

    // neighbor diag-(k-2) cache, alternating; warp0/lane0 seeds cell (0,0)
    float pDa = (warp == 0 && lane == 0) ? 0.f : FINF;
    float pWa = 0.f;
    float pDb = FINF, pWb = 0.f;

    const bool     lane0   = (lane == 0);
    const bool     ringOn  = (warp != 0);
    const unsigned pubFlag = (warp < NWARP - 1 && lane == 31) ? 1u : 0u;
    const unsigned myCnt   = smem_u32(&cnt[warp]);
    const unsigned prevCnt = smem_u32(&cnt[warp > 0 ? warp - 1 : 0]);
    // warp0 reads the dummy slot, offset +1 so srcRing[k-1] stays in-slot
    const float2*  srcRing = ringOn ? &ring[(warp - 1) * RING]
                                    : &ring[7 * RING + 1];
    const unsigned pubRing = smem_u32(&ring[(warp < NWARP - 1 ? warp : 0) * RING]);

    __syncthreads();

    const int kstart = warp * BAND;

    // chunk-0 poll (uniform) + peel of srcRing[kstart-2] for pDa
    if (ringOn) {
        const int need = kstart + SCH - 1;
        unsigned c;
        asm volatile("ld.acquire.cta.shared.u32 %0, [%1];" : "=r"(c) : "r"(prevCnt));
        while ((int)c < need) {
            __nanosleep(32);
            asm volatile("ld.acquire.cta.shared.u32 %0, [%1];" : "=r"(c) : "r"(prevCnt));
        }
        if (lane0) {
            float2 e = srcRing[kstart - 2];
            pDa = e.x; pWa = e.y;
        }
    }

    // cyclic target window: before a group at base k, q1=sT[j0-1],
    // q2=sT[j0-2], q3=sT[j0-3] (j0 = k - i0); q0 loaded in-step.
    float2 q0, q1, q2, q3;
    {
        const int j0f = kstart - i0;
        int u1 = j0f - 1 + PADF;  q1 = sT[u1 + (u1 >> 2)];
        int u2 = j0f - 2 + PADF;  q2 = sT[u2 + (u2 >> 2)];
        int u3 = j0f - 3 + PADF;  q3 = sT[u3 + (u3 >> 2)];
        q0 = q1;  // dead; overwritten by first step
    }

    // ---- one cell: first-min-wins argmin over [diag, up, left] -----------
#define CELL(PX, PY, TQ, UP, DG, WU, WD, LF, WL, OD, OW) do {                \
    const float dx = (PX) - (TQ).x;                                          \
    const float dy = (PY) - (TQ).y;                                          \
    const float c_ = fsqrt_approx(dx * dx + dy * dy);                        \
    const float w_ = fabsf(dx) * s0 + fabsf(dy) * s1;                        \
    const float m1 = fminf((UP), (LF));                                      \
    float ws = ((UP) <= (LF)) ? (WU) : (WL);                                 \
    ws = ((DG) <= m1) ? (WD) : ws;                                           \
    OD = c_ + fminf((DG), m1);                                               \
    OW = w_ + ws;                                                            \
} while (0)

    // ---- one step; outputs written INTO the "prev" register set ----------
#define STEP(K, RINGF,                                                       \
             DC0, DC1, DC2, DC3, WC0, WC1, WC2, WC3,                         \
             DP0, DP1, DP2, DP3, WP0, WP1, WP2, WP3,                         \
             PCD, PCW, PND, PNW, QL, QA, QB, QC) do {                        \
    float nD1 = __shfl_up_sync(0xffffffffu, DC3, 1);                         \
    float nW1 = __shfl_up_sync(0xffffffffu, WC3, 1);                         \
    if (RINGF) {                                                             \
        float2 e_ = srcRing[(K) - 1];                /* broadcast LDS.64 */  \
        nD1 = lane0 ? e_.x : nD1;                                            \
        nW1 = lane0 ? e_.y : nW1;                                            \
    } else {                                                                 \
        nD1 = lane0 ? FINF : nD1;                                            \
        nW1 = lane0 ? 0.f  : nW1;                                            \
    }                                                                        \
    PND = nD1; PNW = nW1;                                                    \
    {   const int u_ = (K) - i0 + PADF;                                      \
        QL = sT[u_ + (u_ >> 2)];                                             \
    }                                                                        \
    CELL(px3, py3, QC, DC2, DP2, WC2, WP2, DC3, WC3, DP3, WP3);              \
    CELL(px2, py2, QB, DC1, DP1, WC1, WP1, DC2, WC2, DP2, WP2);              \
    CELL(px1, py1, QA, DC0, DP0, WC0, WP0, DC1, WC1, DP1, WP1);              \
    CELL(px0, py0, QL, nD1, PCD, nW1, PCW, DC0, WC0, DP0, WP0);              \
    {   unsigned long long v_;                                               \
        asm("mov.b64 %0, {%1, %2};" : "=l"(v_) : "f"(DP3), "f"(WP3));        \
        asm volatile("{\n\t.reg .pred p;\n\tsetp.ne.u32 p, %0, 0;\n\t"       \
                     "@p st.shared.b64 [%1], %2;\n\t}"                       \
                     :: "r"(pubFlag), "r"(pubRing + (unsigned)((K) * 8)),    \
                        "l"(v_) : "memory");                                 \
    }                                                                        \
} while (0)

    // 4 steps: D-role period 2, window rotation period 4 -> names restored
#define GROUP4(KB, RINGF) do {                                               \
    STEP((KB) + 0, RINGF, Da0, Da1, Da2, Da3, Wa0, Wa1, Wa2, Wa3,            \
         Db0, Db1, Db2, Db3, Wb0, Wb1, Wb2, Wb3,                             \
         pDa, pWa, pDb, pWb, q0, q1, q2, q3);                                \
    STEP((KB) + 1, RINGF, Db0, Db1, Db2, Db3, Wb0, Wb1, Wb2, Wb3,            \
         Da0, Da1, Da2, Da3, Wa0, Wa1, Wa2, Wa3,                             \
         pDb, pWb, pDa, pWa, q3, q0, q1, q2);                                \
    STEP((KB) + 2, RINGF, Da0, Da1, Da2, Da3, Wa0, Wa1, Wa2, Wa3,            \
         Db0, Db1, Db2, Db3, Wb0, Wb1, Wb2, Wb3,                             \
         pDa, pWa, pDb, pWb, q2, q3, q0, q1);                                \
    STEP((KB) + 3, RINGF, Db0, Db1, Db2, Db3, Wb0, Wb1, Wb2, Wb3,            \
         Da0, Da1, Da2, Da3, Wa0, Wa1, Wa2, Wa3,                             \
         pDb, pWb, pDa, pWa, q1, q2, q3, q0);                                \
} while (0)

#define DTW_RELEASE(VAL) do {                                                \
    asm volatile("{\n\t.reg .pred p;\n\tsetp.ne.u32 p, %0, 0;\n\t"           \
                 "@p st.release.cta.shared.u32 [%1], %2;\n\t}"               \
                 :: "r"(pubFlag), "r"(myCnt), "r"((unsigned)(VAL))           \
                 : "memory");                                                \
} while (0)
    // ----------------------------------------------------------------------

    // Phase A: 64 chunks x 16 steps (4 groups), ring-fed
    for (int c = 0; c < MM / SCH; ++c) {
        const int kbase = kstart + c * SCH;
        if (ringOn & (c != 0)) {                      // uniform poll per chunk
            const int need = kbase + SCH - 1;
            unsigned cv;
            asm volatile("ld.acquire.cta.shared.u32 %0, [%1];" : "=r"(cv) : "r"(prevCnt));
            while ((int)cv < need) {
                __nanosleep(32);
                asm volatile("ld.acquire.cta.shared.u32 %0, [%1];" : "=r"(cv) : "r"(prevCnt));
            }
        }
#pragma unroll 1
        for (int g = 0; g < SCH / 4; ++g)
            GROUP4(kbase + g * 4, true);
        DTW_RELEASE(kbase + SCH);
    }

    // Phase B: 8 chunks x 16 steps, lane0 neighbor statically FINF.
    // 127 real steps + 1 dummy (rel=1151): dummy's outputs land in the
    // "a" set / unread ring index, so the real result (written into the
    // "b" set at rel=1150) is preserved.
    for (int c = 0; c < 8; ++c) {
        const int kbase = kstart + MM + c * SCH;
#pragma unroll 1
        for (int g = 0; g < SCH / 4; ++g)
            GROUP4(kbase + g * 4, false);
        DTW_RELEASE(kbase + SCH);
    }

    if (tid == TT - 1)                 // rel=1150 output: Wb3 == W[N-1][M-1]
        g_partial[b] = Wb3;
}

__global__ void dtw_reduce_kernel(float* __restrict__ out, int B)
{
    int l = threadIdx.x;
    float s = 0.f;
    if (l < B)      s += g_partial[l];
    if (l + 32 < B) s += g_partial[l + 32];
#pragma unroll
    for (int o = 16; o; o >>= 1) s += __shfl_xor_sync(0xffffffffu, s, o);
    if (l == 0) out[0] = s;
}

extern "C" void kernel_launch(void* const* d_in, const int* in_sizes, int n_in,
                              void* d_out, int out_size)
{
    const float* preds   = (const float*)d_in[0];
    const float* targs   = (const float*)d_in[1];
    const float* subcoef = (const float*)d_in[2];
    float* out = (float*)d_out;

    int B = in_sizes[0] / (NN * 4);
    if (B < 1) B = 1;
    if (B > 64) B = 64;

    cudaFuncSetAttribute(dtw_forward_kernel,
                         cudaFuncAttributeMaxDynamicSharedMemorySize, SMEM_BYTES);

    dtw_forward_kernel<<<B, TT, SMEM_BYTES>>>(preds, targs, subcoef);
    dtw_reduce_kernel<<<1, 32>>>(out, B);
}

// round 13
// speedup vs baseline: 1.7950x; 1.0118x over previous
#include <cuda_runtime.h>

// DTW loss: 32 independent 1024x1024 wavefront DPs, fused with path-loss
// accumulation (W[i,j] = w(i,j) + W[argmin-pred]) -> no backtrack needed.
//
// R12: R11 (role-swap register renaming, branch-free) + issue diet:
//  - immediate-offset addressing: chunk-base registers; all hot LDS/STS are
//    [R+imm]; target swizzle address is carried (+80B/chunk), not recomputed
//  - packed add.rn.f32x2 distance (targets staged NEGATED as float2)
//  - unconditional STS publish (non-publishers write a dummy slot)
//  - SCH=8 chunks (less skew, finer tail release)

#define NN 1024
#define MM 1024
#define TT 256               // threads per block
#define NWARP 8
#define BAND 128             // rows per warp stage (4 rows/thread)
#define RING 2048
#define SCH 8                // diagonals per sync chunk

#define FINF (__int_as_float(0x7f800000))
#define SENT 1.0e18f

__device__ float g_partial[64];

static __forceinline__ __device__ float fsqrt_approx(float x) {
    float r;
    asm("sqrt.approx.f32 %0, %1;" : "=f"(r) : "f"(x));
    return r;
}
static __forceinline__ __device__ unsigned smem_u32(const void* p) {
    return (unsigned)__cvta_generic_to_shared(p);
}

// packed negated-target array: logical j in [-PADF, ...], idx = u + u/4
#define PADF 127
#define STN2 1600
#define NRING 8              // slots 0..6 producers, slot 7 = FINF dummy
#define SMEM_BYTES (NRING * RING * 8 + STN2 * 8 + 32 + 64)

__global__ void __launch_bounds__(TT, 1)
dtw_forward_kernel(const float* __restrict__ preds,
                   const float* __restrict__ targs,
                   const float* __restrict__ subcoef)
{
    extern __shared__ unsigned char smem_raw[];
    float2*   ring = (float2*)smem_raw;               // [NRING][RING]
    float2*   sT   = (float2*)(ring + NRING * RING);  // [STN2] negated+swizzled
    unsigned* cnt  = (unsigned*)(sT + STN2);          // [8] progress counters
    // 64B dummy publish area right after cnt
    const unsigned dummyB = smem_u32(cnt + 8);

    const int b    = blockIdx.x;
    const int tid  = threadIdx.x;
    const int lane = tid & 31;
    const int warp = tid >> 5;

    const float* __restrict__ pb = preds + (size_t)b * NN * 4;
    const float* __restrict__ tb = targs + (size_t)b * MM * 4;

    // stage NEGATED targets with sentinel pad
    for (int u = tid; u < PADF + MM + BAND + 1; u += TT) {
        int j = u - PADF;
        int idx = u + (u >> 2);
        bool in = (unsigned)j < (unsigned)MM;
        int jc = in ? j : 0;
        sT[idx] = in ? make_float2(-tb[jc * 4 + 0], -tb[jc * 4 + 1])
                     : make_float2(-SENT, -SENT);
    }
    // prefill warp0's dummy ring slot with {FINF, 0}
    for (int u = tid; u < RING; u += TT)
        ring[7 * RING + u] = make_float2(FINF, 0.f);
    if (tid < NWARP) cnt[tid] = 0;

    const float s0 = subcoef[0];
    const float s1 = subcoef[1];

    const int i0 = tid * 4;            // first owned row
    unsigned long long P0, P1, P2, P3; // packed (px, py) per owned row
    {
        float x, y;
        x = pb[(i0 + 0) * 4 + 0]; y = pb[(i0 + 0) * 4 + 1];
        asm("mov.b64 %0, {%1, %2};" : "=l"(P0) : "f"(x), "f"(y));
        x = pb[(i0 + 1) * 4 + 0]; y = pb[(i0 + 1) * 4 + 1];
        asm("mov.b64 %0, {%1, %2};" : "=l"(P1) : "f"(x), "f"(y));
        x = pb[(i0 + 2) * 4 + 0]; y = pb[(i0 + 2) * 4 + 1];
        asm("mov.b64 %0, {%1, %2};" : "=l"(P2) : "f"(x), "f"(y));
        x = pb[(i0 + 3) * 4 + 0]; y = pb[(i0 + 3) * 4 + 1];
        asm("mov.b64 %0, {%1, %2};" : "=l"(P3) : "f"(x), "f"(y));
    }

    // role-alternating diag sets: "a" = diag k-1, "b" = diag k-2 at even rel
    float Da0 = FINF, Da1 = FINF, Da2 = FINF, Da3 = FINF;
    float Db0 = FINF, Db1 = FINF, Db2 = FINF, Db3 = FINF;
    float Wa0 = 0.f,  Wa1 = 0.f,  Wa2 = 0.f,  Wa3 = 0.f;
    float Wb0 = 0.f,  Wb1 = 0.f,  Wb2 = 0.f,  Wb3 = 0.f;
    float pDa = (warp == 0 && lane == 0) ? 0.f : FINF;
    float pWa = 0.f;
    float pDb = FINF, pWb = 0.f;

    const bool     lane0   = (lane == 0);
    const bool     ringOn  = (warp != 0);
    const unsigned pubFlag = (warp < NWARP - 1 && lane == 31) ? 1u : 0u;
    const unsigned myCnt   = smem_u32(&cnt[warp]);
    const unsigned prevCnt = smem_u32(&cnt[warp > 0 ? warp - 1 : 0]);
    const float2*  srcRing = ringOn ? &ring[(warp - 1) * RING]
                                    : &ring[7 * RING + 1];

    const int kstart = warp * BAND;

    // carried addresses (chunk bases; hot loop uses [R+imm])
    unsigned srcB = smem_u32(srcRing + kstart) - 8u;             // ring[k-1]
    unsigned pubB = pubFlag ? (smem_u32(&ring[warp * RING]) + (unsigned)kstart * 8u)
                            : dummyB;
    const unsigned incB = pubFlag ? 64u : 0u;
    unsigned tB;
    {
        const int u0 = kstart + PADF - i0;        // in [3, 127]
        tB = smem_u32(sT) + (unsigned)(u0 + (u0 >> 2)) * 8u;
    }

    __syncthreads();

    // chunk-0 poll (uniform) + peel of srcRing[kstart-2] for pDa
    if (ringOn) {
        const int need = kstart + SCH - 1;
        unsigned c;
        asm volatile("ld.acquire.cta.shared.u32 %0, [%1];" : "=r"(c) : "r"(prevCnt));
        while ((int)c < need) {
            __nanosleep(32);
            asm volatile("ld.acquire.cta.shared.u32 %0, [%1];" : "=r"(c) : "r"(prevCnt));
        }
        if (lane0) {
            float2 e = srcRing[kstart - 2];
            pDa = e.x; pWa = e.y;
        }
    }

    // cyclic target window prefetch: q1=sT[u0-1], q2=sT[u0-2], q3=sT[u0-3]
    unsigned long long q0, q1, q2, q3;
    {
        const unsigned long long* sTu = (const unsigned long long*)sT;
        const int u0 = kstart + PADF - i0;
        int u;
        u = u0 - 1; q1 = sTu[u + (u >> 2)];
        u = u0 - 2; q2 = sTu[u + (u >> 2)];
        u = u0 - 3; q3 = sTu[u + (u >> 2)];
        q0 = q1;   // dead; overwritten by first step
    }

    // ---- one cell: first-min-wins argmin over [diag, up, left] -----------
#define CELL(PP, TQ, UP, DG, WU, WD, LF, WL, OD, OW) do {                    \
    unsigned long long dxy_;                                                 \
    asm("add.rn.f32x2 %0, %1, %2;" : "=l"(dxy_) : "l"(PP), "l"(TQ));         \
    float dx_, dy_;                                                          \
    asm("mov.b64 {%0, %1}, %2;" : "=f"(dx_), "=f"(dy_) : "l"(dxy_));         \
    const float c_ = fsqrt_approx(fmaf(dy_, dy_, dx_ * dx_));                \
    const float w_ = fmaf(fabsf(dy_), s1, fabsf(dx_) * s0);                  \
    const float m1 = fminf((UP), (LF));                                      \
    float ws = ((UP) <= (LF)) ? (WU) : (WL);                                 \
    ws = ((DG) <= m1) ? (WD) : ws;                                           \
    OD = c_ + fminf((DG), m1);                                               \
    OW = w_ + ws;                                                            \
} while (0)

    // ---- one step; outputs written INTO the "prev" register set ----------
#define STEP(S, RINGF, TOFF,                                                 \
             DC0, DC1, DC2, DC3, WC0, WC1, WC2, WC3,                         \
             DP0, DP1, DP2, DP3, WP0, WP1, WP2, WP3,                         \
             PCD, PCW, PND, PNW, QL, QA, QB, QC) do {                        \
    float nD1 = __shfl_up_sync(0xffffffffu, DC3, 1);                         \
    float nW1 = __shfl_up_sync(0xffffffffu, WC3, 1);                         \
    if (RINGF) {                                                             \
        float rD_, rW_;                                                      \
        asm("ld.shared.v2.f32 {%0, %1}, [%2+%3];"                            \
            : "=f"(rD_), "=f"(rW_) : "r"(srcB), "n"((S) * 8));               \
        nD1 = lane0 ? rD_ : nD1;                                             \
        nW1 = lane0 ? rW_ : nW1;                                             \
    } else {                                                                 \
        nD1 = lane0 ? FINF : nD1;                                            \
        nW1 = lane0 ? 0.f  : nW1;                                            \
    }                                                                        \
    PND = nD1; PNW = nW1;                                                    \
    asm("ld.shared.b64 %0, [%1+%2];" : "=l"(QL) : "r"(tB), "n"(TOFF));       \
    CELL(P3, QC, DC2, DP2, WC2, WP2, DC3, WC3, DP3, WP3);                    \
    CELL(P2, QB, DC1, DP1, WC1, WP1, DC2, WC2, DP2, WP2);                    \
    CELL(P1, QA, DC0, DP0, WC0, WP0, DC1, WC1, DP1, WP1);                    \
    CELL(P0, QL, nD1, PCD, nW1, PCW, DC0, WC0, DP0, WP0);                    \
    asm volatile("st.shared.v2.f32 [%0+%1], {%2, %3};"                       \
                 :: "r"(pubB), "n"((S) * 8), "f"(DP3), "f"(WP3) : "memory"); \
} while (0)

    // 8 steps = 2 full role/window rotations; target offsets {0,16,24,32,
    // 40,56,64,72} encode the carried swizzle walk (u%4 phase = 3 at S=0)
#define CHUNK8(RINGF) do {                                                   \
    STEP(0, RINGF, 0,  Da0,Da1,Da2,Da3, Wa0,Wa1,Wa2,Wa3,                     \
         Db0,Db1,Db2,Db3, Wb0,Wb1,Wb2,Wb3, pDa,pWa,pDb,pWb, q0,q1,q2,q3);    \
    STEP(1, RINGF, 16, Db0,Db1,Db2,Db3, Wb0,Wb1,Wb2,Wb3,                     \
         Da0,Da1,Da2,Da3, Wa0,Wa1,Wa2,Wa3, pDb,pWb,pDa,pWa, q3,q0,q1,q2);    \
    STEP(2, RINGF, 24, Da0,Da1,Da2,Da3, Wa0,Wa1,Wa2,Wa3,                     \
         Db0,Db1,Db2,Db3, Wb0,Wb1,Wb2,Wb3, pDa,pWa,pDb,pWb, q2,q3,q0,q1);    \
    STEP(3, RINGF, 32, Db0,Db1,Db2,Db3, Wb0,Wb1,Wb2,Wb3,                     \
         Da0,Da1,Da2,Da3, Wa0,Wa1,Wa2,Wa3, pDb,pWb,pDa,pWa, q1,q2,q3,q0);    \
    STEP(4, RINGF, 40, Da0,Da1,Da2,Da3, Wa0,Wa1,Wa2,Wa3,                     \
         Db0,Db1,Db2,Db3, Wb0,Wb1,Wb2,Wb3, pDa,pWa,pDb,pWb, q0,q1,q2,q3);    \
    STEP(5, RINGF, 56, Db0,Db1,Db2,Db3, Wb0,Wb1,Wb2,Wb3,                     \
         Da0,Da1,Da2,Da3, Wa0,Wa1,Wa2,Wa3, pDb,pWb,pDa,pWa, q3,q0,q1,q2);    \
    STEP(6, RINGF, 64, Da0,Da1,Da2,Da3, Wa0,Wa1,Wa2,Wa3,                     \
         Db0,Db1,Db2,Db3, Wb0,Wb1,Wb2,Wb3, pDa,pWa,pDb,pWb, q2,q3,q0,q1);    \
    STEP(7, RINGF, 72, Db0,Db1,Db2,Db3, Wb0,Wb1,Wb2,Wb3,                     \
         Da0,Da1,Da2,Da3, Wa0,Wa1,Wa2,Wa3, pDb,pWb,pDa,pWa, q1,q2,q3,q0);    \
} while (0)

#define DTW_RELEASE(VAL) do {                                                \
    asm volatile("{\n\t.reg .pred p;\n\tsetp.ne.u32 p, %0, 0;\n\t"           \
                 "@p st.release.cta.shared.u32 [%1], %2;\n\t}"               \
                 :: "r"(pubFlag), "r"(myCnt), "r"((unsigned)(VAL))           \
                 : "memory");                                                \
} while (0)
    // ----------------------------------------------------------------------

    int kb = kstart;

    // Phase A: 128 chunks x 8 steps, ring-fed
    for (int c = 0; c < MM / SCH; ++c) {
        if (ringOn & (c != 0)) {                      // uniform poll per chunk
            const int need = kb + SCH - 1;
            unsigned cv;
            asm volatile("ld.acquire.cta.shared.u32 %0, [%1];" : "=r"(cv) : "r"(prevCnt));
            while ((int)cv < need) {
                __nanosleep(32);
                asm volatile("ld.acquire.cta.shared.u32 %0, [%1];" : "=r"(cv) : "r"(prevCnt));
            }
        }
        CHUNK8(true);
        kb += SCH;
        DTW_RELEASE(kb);
        srcB += SCH * 8;
        pubB += incB;
        tB   += 80;
    }

    // Phase B: 16 chunks x 8 steps, lane0 neighbor statically FINF.
    // 127 real steps + 1 dummy (rel=1151, outputs land in the "a" set /
    // unread ring index) -> result at rel=1150 is preserved in the "b" set.
    for (int c = 0; c < 16; ++c) {
        CHUNK8(false);
        kb += SCH;
        DTW_RELEASE(kb);
        pubB += incB;
        tB   += 80;
    }

    if (tid == TT - 1)                 // rel=1150 output: Wb3 == W[N-1][M-1]
        g_partial[b] = Wb3;
}

__global__ void dtw_reduce_kernel(float* __restrict__ out, int B)
{
    int l = threadIdx.x;
    float s = 0.f;
    if (l < B)      s += g_partial[l];
    if (l + 32 < B) s += g_partial[l + 32];
#pragma unroll
    for (int o = 16; o; o >>= 1) s += __shfl_xor_sync(0xffffffffu, s, o);
    if (l == 0) out[0] = s;
}

extern "C" void kernel_launch(void* const* d_in, const int* in_sizes, int n_in,
                              void* d_out, int out_size)
{
    const float* preds   = (const float*)d_in[0];
    const float* targs   = (const float*)d_in[1];
    const float* subcoef = (const float*)d_in[2];
    float* out = (float*)d_out;

    int B = in_sizes[0] / (NN * 4);
    if (B < 1) B = 1;
    if (B > 64) B = 64;

    cudaFuncSetAttribute(dtw_forward_kernel,
                         cudaFuncAttributeMaxDynamicSharedMemorySize, SMEM_BYTES);

    dtw_forward_kernel<<<B, TT, SMEM_BYTES>>>(preds, targs, subcoef);
    dtw_reduce_kernel<<<1, 32>>>(out, B);
}